// round 10
// baseline (speedup 1.0000x reference)
#include <cuda_runtime.h>
#include <cuda_fp16.h>
#include <cstdint>

// ---------------------------------------------------------------------------
// QuadraticAttentionModule via fp16 mma.sync.m16n8k16.
//   out[b,o] = bias[o] + sum_k X[b,k] * W[o,k]
//   X[b,k] = xf[b,k] (k<1024) else xf[b,i]*xf[b,j]
// GEMM: M=o(1024), N=b(64), K=525824. X pre-materialized as fp16.
// R10: KT=128 (108 stages, half the barriers), W loads in 2 batches
// interleaved with compute to bound register pressure and overlap STS.
// ---------------------------------------------------------------------------

#define IN_DIM 1024
#define NB     64
#define NOUT   1024
#define KTOT   525824
#define KT     128
#define STAGES (KTOT / KT)       // 4108
#define KS     38                // 8*38 = 304 CTAs = 2/SM
#define MT     8
#define SPLIT_Q (STAGES / KS)    // 108
#define SPLIT_R (STAGES % KS)    // 4

#define WSTR     136             // halves per smem row (128 + 8 pad), 272B
#define W_TILE_H (128 * WSTR)    // 34816 B
#define X_TILE_H (64 * WSTR)     // 17408 B
#define STAGE_B  ((W_TILE_H + X_TILE_H) * 2)   // 52224 B
#define SMEM_BYTES (2 * STAGE_B)               // 104448 B

// Scratch (__device__ globals per allocation rules)
__device__ int    d_ij[KTOT];
__device__ __align__(16) __half d_Xh[(size_t)NB * KTOT];   // [b][k] fp16 RN
__device__ float  d_partial[(size_t)KS * NOUT * NB];       // [split][o][b]

// --------------------------- PTX helpers ------------------------------------

__device__ __forceinline__ uint32_t smem_u32(const void* p) {
    uint32_t a;
    asm("{ .reg .u64 t; cvta.to.shared.u64 t, %1; cvt.u32.u64 %0, t; }" : "=r"(a) : "l"(p));
    return a;
}
__device__ __forceinline__ void cp16(uint32_t saddr, const void* gptr) {
    asm volatile("cp.async.cg.shared.global [%0], [%1], 16;"
                 :: "r"(saddr), "l"(gptr) : "memory");
}
__device__ __forceinline__ void ldsm4(uint32_t* r, uint32_t addr) {
    asm volatile("ldmatrix.sync.aligned.m8n8.x4.shared.b16 {%0,%1,%2,%3}, [%4];"
                 : "=r"(r[0]), "=r"(r[1]), "=r"(r[2]), "=r"(r[3]) : "r"(addr));
}
__device__ __forceinline__ void mma16816(float* d, const uint32_t* a, const uint32_t* b) {
    asm volatile(
        "mma.sync.aligned.m16n8k16.row.col.f32.f16.f16.f32 "
        "{%0,%1,%2,%3}, {%4,%5,%6,%7}, {%8,%9}, {%0,%1,%2,%3};\n"
        : "+f"(d[0]), "+f"(d[1]), "+f"(d[2]), "+f"(d[3])
        : "r"(a[0]), "r"(a[1]), "r"(a[2]), "r"(a[3]), "r"(b[0]), "r"(b[1]));
}
// Pack two fp32 -> one u32 of two rn-rounded fp16 (lo = a, hi = b).
__device__ __forceinline__ uint32_t packh2(float a, float b) {
    uint32_t r;
    asm("cvt.rn.f16x2.f32 %0, %2, %1;" : "=r"(r) : "f"(a), "f"(b));
    return r;
}

// --------------------------- prep kernels ----------------------------------

__device__ __forceinline__ long long triu_off(long long i) {
    return i * IN_DIM - i * (i - 1) / 2;
}

__global__ void qa_ij() {
    int k = blockIdx.x * blockDim.x + threadIdx.x;
    if (k >= KTOT) return;
    if (k < IN_DIM) { d_ij[k] = (k << 16) | 0xFFFF; return; }
    long long p = k - IN_DIM;
    double nn = 2.0 * IN_DIM + 1.0;
    int i = (int)((nn - sqrt(nn * nn - 8.0 * (double)p)) * 0.5);
    if (i < 0) i = 0;
    if (i > IN_DIM - 1) i = IN_DIM - 1;
    while (i > 0 && triu_off(i) > p) --i;
    while (i < IN_DIM - 1 && triu_off(i + 1) <= p) ++i;
    int j = i + (int)(p - triu_off(i));
    d_ij[k] = (i << 16) | j;
}

// Materialize X[b][k] in fp16 (round-to-nearest).
__global__ void qa_buildXh(const float* __restrict__ in) {
    int k = blockIdx.x * 256 + threadIdx.x;    // grid.x = KTOT/256 = 2054
    int b = blockIdx.y;
    int ij = d_ij[k];
    int i = ij >> 16, j = ij & 0xFFFF;
    float v = in[b * IN_DIM + i];
    if (j != 0xFFFF) v *= in[b * IN_DIM + j];
    d_Xh[(size_t)b * KTOT + k] = __float2half_rn(v);
}

// --------------------------- main GEMM -------------------------------------
// CTA tile 128(M) x 64(N) x KT=128. 8 warps as 2(M,64) x 4(N,16).
// Per slot: W [128][136] halves, X [64][136] halves (rows padded to 272B).

__global__ __launch_bounds__(256, 2)
void qa_main(const float* __restrict__ W) {
    extern __shared__ __align__(128) char smem[];
    const uint32_t sb = smem_u32(smem);
    const int tid = threadIdx.x, lane = tid & 31, wid = tid >> 5;
    const int warpM = wid >> 2, warpN = wid & 3;

    const int o_base = blockIdx.x * 128;
    const int split  = blockIdx.y;
    const int s0 = split * SPLIT_Q + min(split, SPLIT_R);
    const int s1 = s0 + SPLIT_Q + (split < SPLIT_R ? 1 : 0);

    // --- W producer: batch bt (0/1), step j=0..7 -> row (tid>>5)+8j+64bt,
    // 16B chunk tid&31. One warp = one full 512B row (4 complete lines).
    const int wr0 = tid >> 5, wc = tid & 31;
    const float* wptr = W + (size_t)(o_base + wr0) * KTOT + (size_t)s0 * KT + wc * 4;
    const uint32_t wsto = wr0 * 272 + wc * 8;          // (+ row_delta*272)

    // --- X producer: step j=0..3 -> row (tid>>4)+16j, 16B chunk tid&15.
    const int xr0 = tid >> 4, xc = tid & 15;
    const __half* xptr = d_Xh + (size_t)xr0 * KTOT + (size_t)s0 * KT + xc * 8;
    const uint32_t xsto = xr0 * 272 + xc * 16;         // (+ j*16*272)

    // Fragment base byte offsets within slot (ldmatrix address schemes)
    const uint32_t aoff = ((warpM * 64 + (lane & 15)) * WSTR + ((lane >> 4) * 8)) * 2;
    const uint32_t boff = ((warpN * 16 + ((lane >> 4) * 8) + (lane & 7)) * WSTR
                          + (((lane >> 3) & 1) * 8)) * 2;

    float4 wreg[8];
    float  acc[4][2][4];
    #pragma unroll
    for (int mt = 0; mt < 4; mt++)
        #pragma unroll
        for (int nt = 0; nt < 2; nt++)
            #pragma unroll
            for (int r = 0; r < 4; r++) acc[mt][nt][r] = 0.f;

    auto loadW = [&](int s, int bt) {                  // 8 LDG.128 (rows +64*bt)
        const float* p = wptr + (size_t)(s - s0) * KT + (size_t)(64 * bt) * KTOT;
        #pragma unroll
        for (int j = 0; j < 8; j++)
            wreg[j] = *(const float4*)(p + (size_t)(8 * j) * KTOT);
    };
    auto storeW = [&](int slot, int bt) {
        char* base = smem + slot * STAGE_B + wsto + (64 * bt) * 272;
        #pragma unroll
        for (int j = 0; j < 8; j++) {
            uint2 u;
            u.x = packh2(wreg[j].x, wreg[j].y);
            u.y = packh2(wreg[j].z, wreg[j].w);
            *(uint2*)(base + j * 8 * 272) = u;         // STS.64, conflict-free
        }
    };
    auto cpX = [&](int s, int slot) {                  // 4x 16B per thread
        uint32_t dst = sb + slot * STAGE_B + W_TILE_H * 2 + xsto;
        const __half* p = xptr + (size_t)(s - s0) * KT;
        #pragma unroll
        for (int j = 0; j < 4; j++)
            cp16(dst + j * 16 * 272, p + (size_t)(16 * j) * KTOT);
        asm volatile("cp.async.commit_group;" ::: "memory");
    };
    auto compute = [&](int slot, int k0, int k1) {     // k-steps [k0,k1) of 8
        const uint32_t wbase = sb + slot * STAGE_B;
        const uint32_t xbase = wbase + W_TILE_H * 2;
        #pragma unroll
        for (int ks = k0; ks < k1; ks++) {
            const int kk = ks * 16;
            uint32_t a[4][4], b4[4];
            #pragma unroll
            for (int mt = 0; mt < 4; mt++)
                ldsm4(a[mt], wbase + aoff + (mt * 16 * WSTR + kk) * 2);
            ldsm4(b4, xbase + boff + kk * 2);
            #pragma unroll
            for (int mt = 0; mt < 4; mt++)
                #pragma unroll
                for (int nt = 0; nt < 2; nt++)
                    mma16816(acc[mt][nt], a[mt], b4 + nt * 2);
        }
    };

    // Prologue: fill slot 0
    cpX(s0, 0);
    loadW(s0, 0); storeW(0, 0);
    loadW(s0, 1); storeW(0, 1);
    asm volatile("cp.async.wait_group 0;" ::: "memory");
    __syncthreads();

    for (int s = s0; s < s1; s++) {
        const int cur = (s - s0) & 1, nxt = cur ^ 1;
        const bool more = (s + 1 < s1);
        if (more) { cpX(s + 1, nxt); loadW(s + 1, 0); }
        compute(cur, 0, 3);
        if (more) { storeW(nxt, 0); loadW(s + 1, 1); }
        compute(cur, 3, 7);
        if (more) storeW(nxt, 1);
        compute(cur, 7, 8);
        asm volatile("cp.async.wait_group 0;" ::: "memory");
        __syncthreads();
    }

    // Epilogue: partial[split][o][b], vectorized float2
    float* part = d_partial + (size_t)split * (NOUT * NB);
    #pragma unroll
    for (int mt = 0; mt < 4; mt++)
        #pragma unroll
        for (int nt = 0; nt < 2; nt++) {
            int o  = o_base + warpM * 64 + mt * 16 + (lane >> 2);
            int bb = warpN * 16 + nt * 8 + 2 * (lane & 3);
            *(float2*)&part[(size_t)o * NB + bb] =
                make_float2(acc[mt][nt][0], acc[mt][nt][1]);
            *(float2*)&part[(size_t)(o + 8) * NB + bb] =
                make_float2(acc[mt][nt][2], acc[mt][nt][3]);
        }
}

// --------------------------- reduce ----------------------------------------

__global__ void qa_reduce(const float* __restrict__ bias, float* __restrict__ out) {
    int t = blockIdx.x * blockDim.x + threadIdx.x;  // t = o*64 + b
    int o = t >> 6, b = t & 63;
    float s = bias[o];
    #pragma unroll
    for (int k = 0; k < KS; k++)
        s += d_partial[(size_t)k * (NOUT * NB) + t];   // coalesced reads
    out[(size_t)b * NOUT + o] = s;                     // scattered 4B writes
}

// --------------------------- launch ----------------------------------------

extern "C" void kernel_launch(void* const* d_in, const int* in_sizes, int n_in,
                              void* d_out, int out_size) {
    const float* input_ = (const float*)d_in[0];   // (64,32,32) fp32
    const float* W      = (const float*)d_in[1];   // (1024, 525824) fp32
    const float* bias   = (const float*)d_in[2];   // (1024,) fp32
    float* out = (float*)d_out;                    // (64,32,32) fp32

    cudaFuncSetAttribute(qa_main, cudaFuncAttributeMaxDynamicSharedMemorySize, SMEM_BYTES);

    qa_ij<<<(KTOT + 1023) / 1024, 1024>>>();
    qa_buildXh<<<dim3(KTOT / 256, NB), 256>>>(input_);
    qa_main<<<dim3(MT, KS), 256, SMEM_BYTES>>>(W);
    qa_reduce<<<64, 1024>>>(bias, out);
}